// round 16
// baseline (speedup 1.0000x reference)
#include <cuda_runtime.h>
#include <cuda_fp16.h>
#include <cstdint>

// Problem constants (fixed by the dataset)
#define HH   1024
#define WW   2048
#define GW2  2052            // padded row stride in cells (even, float4-aligned pairs)
#define GH   (HH + 2)        // padded grid height = 1026
#define NCELL (GH * GW2)     // 2,105,352 cells (float2: ~16.8 MB, L2-resident)
#define NPIX (HH * WW)       // 2,097,152
#define COUT 64
#define BN_EPS 1e-5f
#define STATS_BLOCKS 592
#define OUT_BLOCKS 592
#define NWARP 8              // warps per k_output block

// Scratch (static __device__ arrays — zero-initialized at module load).
// Each cell: .x = feature (0 if empty), .y = int bits of (output row + 1); 0 = empty.
__device__ float2 g_cell[NCELL];             // interleaved (feat, idx) grid
__device__ float  g_part[STATS_BLOCKS * 54]; // per-block stat partials
__device__ float  g_wf[9 * COUT];            // BN-folded weights
__device__ float  g_bf[COUT];                // BN-folded bias
__device__ int    g_ctr;                     // last-block counter (reset by last block)

__device__ __forceinline__ uint32_t smem_u32(const void* p) {
    uint32_t a;
    asm("{ .reg .u64 t; cvta.to.shared.u64 t, %1; cvt.u32.u64 %0, t; }"
        : "=r"(a) : "l"(p));
    return a;
}

// ---------------------------------------------------------------------------
// K1: scatter — 4 points per thread, ONE 8 B store per point.
// ---------------------------------------------------------------------------
__global__ __launch_bounds__(256) void k_scatter(
        const int2* __restrict__ coords,
        const float* __restrict__ feats, int n) {
    const int t   = blockIdx.x * blockDim.x + threadIdx.x;
    const int str = gridDim.x * blockDim.x;
    const int nq  = n >> 2;

    for (int i = t; i < nq; i += str) {
        const float4 f  = *reinterpret_cast<const float4*>(feats + 4 * i);
        const int4 c01  = *reinterpret_cast<const int4*>(coords + 4 * i);
        const int4 c23  = *reinterpret_cast<const int4*>(coords + 4 * i + 2);
        const int p = 4 * i;
        g_cell[(c01.x + 1) * GW2 + (c01.y + 1)] = make_float2(f.x, __int_as_float(p + 1));
        g_cell[(c01.z + 1) * GW2 + (c01.w + 1)] = make_float2(f.y, __int_as_float(p + 2));
        g_cell[(c23.x + 1) * GW2 + (c23.y + 1)] = make_float2(f.z, __int_as_float(p + 3));
        g_cell[(c23.z + 1) * GW2 + (c23.w + 1)] = make_float2(f.w, __int_as_float(p + 4));
    }
    for (int i = nq * 4 + t; i < n; i += str) {
        const int2 c = coords[i];
        g_cell[(c.x + 1) * GW2 + (c.y + 1)] = make_float2(feats[i], __int_as_float(i + 1));
    }
}

// ---------------------------------------------------------------------------
// K2: DENSE vectorized stats scan (unchanged from R13) + fused BN fold.
// ---------------------------------------------------------------------------
__global__ __launch_bounds__(256) void k_stats(
        const float* __restrict__ weight,
        const float* __restrict__ gamma,
        const float* __restrict__ beta, int n) {
    float acc[54];
#pragma unroll
    for (int i = 0; i < 54; i++) acc[i] = 0.f;

    const int tid    = blockIdx.x * blockDim.x + threadIdx.x;
    const int stride = gridDim.x * blockDim.x;
    const int nquad  = NPIX / 4;

    for (int Q = tid; Q < nquad; Q += stride) {
        const int q = Q * 4;
        const int y = q >> 11;
        const int x = q & (WW - 1);
        const float2* base = g_cell + y * GW2 + x;

        float v[3][6];
        float mb[4];
#pragma unroll
        for (int r = 0; r < 3; r++) {
            const float4 u0 = *reinterpret_cast<const float4*>(base + r * GW2);
            const float4 u1 = *reinterpret_cast<const float4*>(base + r * GW2 + 2);
            const float4 u2 = *reinterpret_cast<const float4*>(base + r * GW2 + 4);
            v[r][0] = u0.x; v[r][1] = u0.z; v[r][2] = u1.x;
            v[r][3] = u1.z; v[r][4] = u2.x; v[r][5] = u2.z;
            if (r == 1) { mb[0] = u0.w; mb[1] = u1.y; mb[2] = u1.w; mb[3] = u2.y; }
        }
#pragma unroll
        for (int i = 0; i < 4; i++) {
            const float m = (__float_as_int(mb[i]) > 0) ? 1.f : 0.f;
            float s[9];
#pragma unroll
            for (int r = 0; r < 3; r++)
#pragma unroll
                for (int c = 0; c < 3; c++)
                    s[r * 3 + c] = v[r][i + c] * m;
#pragma unroll
            for (int k = 0; k < 9; k++) acc[k] += s[k];
            int idx = 9;
#pragma unroll
            for (int j = 0; j < 9; j++)
#pragma unroll
                for (int k = j; k < 9; k++) acc[idx++] += s[j] * s[k];
        }
    }

    __shared__ float red[54 * 8];
    const int w = threadIdx.x >> 5, lane = threadIdx.x & 31;
#pragma unroll
    for (int i = 0; i < 54; i++) {
        float v2 = acc[i];
#pragma unroll
        for (int o = 16; o; o >>= 1) v2 += __shfl_xor_sync(0xffffffffu, v2, o);
        if (lane == 0) red[i * 8 + w] = v2;
    }
    __syncthreads();
    if (threadIdx.x < 54) {
        float v2 = 0.f;
#pragma unroll
        for (int ww = 0; ww < 8; ww++) v2 += red[threadIdx.x * 8 + ww];
        g_part[blockIdx.x * 54 + threadIdx.x] = v2;
    }

    __shared__ bool is_last;
    __threadfence();
    if (threadIdx.x == 0) {
        int prev = atomicAdd(&g_ctr, 1);
        is_last = (prev == gridDim.x - 1);
    }
    __syncthreads();
    if (!is_last) return;
    if (threadIdx.x == 0) g_ctr = 0;

    __shared__ float st[64];
    {
        const int t = threadIdx.x;
        const int g = t >> 2;
        const int j = t & 3;
        float v2 = 0.f;
        if (g < 54)
            for (int b = j; b < STATS_BLOCKS; b += 4)
                v2 += g_part[b * 54 + g];
        v2 += __shfl_xor_sync(0xffffffffu, v2, 1);
        v2 += __shfl_xor_sync(0xffffffffu, v2, 2);
        if (j == 0 && g < 54) st[g] = v2;
    }
    __syncthreads();

    if (threadIdx.x < COUT) {
        const int t = threadIdx.x;
        float wv[9];
#pragma unroll
        for (int k = 0; k < 9; k++) wv[k] = weight[k * COUT + t];
        const float invn = 1.f / (float)n;

        float mean = 0.f;
#pragma unroll
        for (int k = 0; k < 9; k++) mean += st[k] * wv[k];
        mean *= invn;

        float q = 0.f;
        int idx = 9;
#pragma unroll
        for (int jj = 0; jj < 9; jj++)
#pragma unroll
            for (int k = jj; k < 9; k++) {
                float term = st[idx++] * wv[jj] * wv[k];
                q += (jj == k) ? term : 2.f * term;
            }
        float var   = fmaxf(q * invn - mean * mean, 0.f);
        float scale = gamma[t] * rsqrtf(var + BN_EPS);
#pragma unroll
        for (int k = 0; k < 9; k++) g_wf[k * COUT + t] = wv[k] * scale;
        g_bf[t] = beta[t] - mean * scale;
    }
}

// ---------------------------------------------------------------------------
// K4: HMMA output pass (mma.sync m16n8k16 — baseline PTX, no sm_103a needed).
//     Warp-autonomous 32-pixel tiles:
//       stage: lane = pixel; 9 taps + bias(1.0) -> fp16 hi + fp16 lo residual,
//              written as 16-half rows (48 B stride: conflict-free STS.128,
//              16 B-aligned for ldmatrix). oidx -> smem.
//       math:  2 rowgroups x [ldmatrix.x4 (hi,lo) + 8 nblk x 3 mma
//              (Ah*Bh + Al*Bh + Ah*Bl — fp16 products exact in fp32,
//              dropped lo*lo ~ 2e-7)]. B frags register-resident.
//       store: C frag rows = pixels; predicated streaming STG.64
//              (32 B sector-perfect chunks of each 256 B output row).
// ---------------------------------------------------------------------------
__device__ __forceinline__ float bval(int k, int n) {
    return (k < 9) ? g_wf[k * COUT + n] : ((k == 9) ? g_bf[n] : 0.f);
}

__global__ __launch_bounds__(256, 3) void k_output(float* __restrict__ out) {
    // per-warp: hi tile 32 rows x 48 B = 384 words, lo tile 384 words, oidx 32
    __shared__ uint32_t s_a[NWARP][768];
    __shared__ int      s_ox[NWARP][32];

    const int tid  = threadIdx.x;
    const int lane = tid & 31;
    const int wid  = tid >> 5;
    const int bg   = lane >> 2;     // fragment group id (0..7)
    const int btg  = lane & 3;      // thread-in-group (0..3)

    // --- build B fragments (hi + lo) once; n = nblk*8 + bg, k = btg*2+{0,1}+8r
    uint32_t bh[8][2], bl[8][2];
#pragma unroll
    for (int nb = 0; nb < 8; nb++) {
        const int nch = nb * 8 + bg;
#pragma unroll
        for (int r = 0; r < 2; r++) {
            const int k0 = btg * 2 + r * 8;
            const float w0 = bval(k0, nch), w1 = bval(k0 + 1, nch);
            const __half h0 = __float2half_rn(w0), h1 = __float2half_rn(w1);
            const __half l0 = __float2half_rn(w0 - __half2float(h0));
            const __half l1 = __float2half_rn(w1 - __half2float(h1));
            __half2 hh = __halves2half2(h0, h1);
            __half2 ll = __halves2half2(l0, l1);
            bh[nb][r] = *reinterpret_cast<uint32_t*>(&hh);
            bl[nb][r] = *reinterpret_cast<uint32_t*>(&ll);
        }
    }

    const uint32_t abase_hi = smem_u32(&s_a[wid][0]);
    const uint32_t abase_lo = abase_hi + 1536;
    float2* out2 = reinterpret_cast<float2*>(out);

    const int gw = (blockIdx.x * 256 + tid) >> 5;
    const int nwarps = (gridDim.x * 256) >> 5;
    const int ntiles = NPIX / 32;   // 65536

    for (int tile = gw; tile < ntiles; tile += nwarps) {
        const int q0 = tile * 32;
        const int y  = q0 >> 11;
        const int x0 = q0 & (WW - 1);

        // --- stage A (lane = its own pixel) ---
        const float2* rb = g_cell + y * GW2 + x0 + lane;
        const float2 center = rb[GW2 + 1];
        s_ox[wid][lane] = __float_as_int(center.y);

        float s[9];
        s[0] = rb[0].x;       s[1] = rb[1].x;       s[2] = rb[2].x;
        s[3] = rb[GW2].x;     s[4] = center.x;      s[5] = rb[GW2 + 2].x;
        s[6] = rb[2*GW2].x;   s[7] = rb[2*GW2+1].x; s[8] = rb[2*GW2+2].x;

        __half h[10], lo[10];
#pragma unroll
        for (int i = 0; i < 9; i++) {
            h[i]  = __float2half_rn(s[i]);
            lo[i] = __float2half_rn(s[i] - __half2float(h[i]));
        }
        h[9]  = __float2half_rn(1.0f);
        lo[9] = __float2half_rn(0.0f);

        uint32_t ph[5], pl[5];
#pragma unroll
        for (int i = 0; i < 5; i++) {
            __half2 a2 = __halves2half2(h[2*i], h[2*i+1]);
            __half2 b2 = __halves2half2(lo[2*i], lo[2*i+1]);
            ph[i] = *reinterpret_cast<uint32_t*>(&a2);
            pl[i] = *reinterpret_cast<uint32_t*>(&b2);
        }
        {
            uint4* rh = reinterpret_cast<uint4*>(&s_a[wid][lane * 12]);
            rh[0] = make_uint4(ph[0], ph[1], ph[2], ph[3]);
            rh[1] = make_uint4(ph[4], 0u, 0u, 0u);
            uint4* rl = reinterpret_cast<uint4*>(&s_a[wid][384 + lane * 12]);
            rl[0] = make_uint4(pl[0], pl[1], pl[2], pl[3]);
            rl[1] = make_uint4(pl[4], 0u, 0u, 0u);
        }
        __syncwarp();

        // --- 2 rowgroups of 16 pixels ---
#pragma unroll
        for (int rg = 0; rg < 2; rg++) {
            const int ox0 = s_ox[wid][rg * 16 + bg];
            const int ox1 = s_ox[wid][rg * 16 + bg + 8];

            const uint32_t roff =
                (uint32_t)(rg * 16 + (lane & 7) + ((lane >> 3) & 1) * 8) * 48 +
                (uint32_t)(lane >> 4) * 16;
            uint32_t ah0, ah1, ah2, ah3, al0, al1, al2, al3;
            asm volatile("ldmatrix.sync.aligned.m8n8.x4.shared.b16 {%0,%1,%2,%3}, [%4];"
                : "=r"(ah0), "=r"(ah1), "=r"(ah2), "=r"(ah3)
                : "r"(abase_hi + roff));
            asm volatile("ldmatrix.sync.aligned.m8n8.x4.shared.b16 {%0,%1,%2,%3}, [%4];"
                : "=r"(al0), "=r"(al1), "=r"(al2), "=r"(al3)
                : "r"(abase_lo + roff));

#pragma unroll
            for (int nb = 0; nb < 8; nb++) {
                float c0 = 0.f, c1 = 0.f, c2 = 0.f, c3 = 0.f;
                asm volatile(
                    "mma.sync.aligned.m16n8k16.row.col.f32.f16.f16.f32 "
                    "{%0,%1,%2,%3}, {%4,%5,%6,%7}, {%8,%9}, {%0,%1,%2,%3};"
                    : "+f"(c0), "+f"(c1), "+f"(c2), "+f"(c3)
                    : "r"(ah0), "r"(ah1), "r"(ah2), "r"(ah3),
                      "r"(bh[nb][0]), "r"(bh[nb][1]));
                asm volatile(
                    "mma.sync.aligned.m16n8k16.row.col.f32.f16.f16.f32 "
                    "{%0,%1,%2,%3}, {%4,%5,%6,%7}, {%8,%9}, {%0,%1,%2,%3};"
                    : "+f"(c0), "+f"(c1), "+f"(c2), "+f"(c3)
                    : "r"(al0), "r"(al1), "r"(al2), "r"(al3),
                      "r"(bh[nb][0]), "r"(bh[nb][1]));
                asm volatile(
                    "mma.sync.aligned.m16n8k16.row.col.f32.f16.f16.f32 "
                    "{%0,%1,%2,%3}, {%4,%5,%6,%7}, {%8,%9}, {%0,%1,%2,%3};"
                    : "+f"(c0), "+f"(c1), "+f"(c2), "+f"(c3)
                    : "r"(ah0), "r"(ah1), "r"(ah2), "r"(ah3),
                      "r"(bl[nb][0]), "r"(bl[nb][1]));

                // C layout: c0,c1 -> row bg,   cols 2*btg,2*btg+1 (+ nb*8)
                //           c2,c3 -> row bg+8, same cols
                const int colf2 = nb * 4 + btg;   // float2 column index
                if (ox0 > 0) {
                    float2 v = make_float2(fmaxf(c0, 0.f), fmaxf(c1, 0.f));
                    __stcs(&out2[(size_t)(ox0 - 1) * 32 + colf2], v);
                }
                if (ox1 > 0) {
                    float2 v = make_float2(fmaxf(c2, 0.f), fmaxf(c3, 0.f));
                    __stcs(&out2[(size_t)(ox1 - 1) * 32 + colf2], v);
                }
            }
        }
        __syncwarp();
    }
}

// ---------------------------------------------------------------------------
// Launch: inputs are feats[N,1] f32, weight[9,1,64] f32, gamma[64], beta[64],
//         coords[N,2] i32. Output: [N,64] f32.
// ---------------------------------------------------------------------------
extern "C" void kernel_launch(void* const* d_in, const int* in_sizes, int n_in,
                              void* d_out, int out_size) {
    const float* feats  = (const float*)d_in[0];
    const float* weight = (const float*)d_in[1];
    const float* gamma  = (const float*)d_in[2];
    const float* beta   = (const float*)d_in[3];
    const int2*  coords = (const int2*)d_in[4];
    const int n = in_sizes[0];   // N (C_IN = 1)

    k_scatter<<<1024, 256>>>(coords, feats, n);
    k_stats<<<STATS_BLOCKS, 256>>>(weight, gamma, beta, n);
    k_output<<<OUT_BLOCKS, 256>>>((float*)d_out);
}